// round 13
// baseline (speedup 1.0000x reference)
#include <cuda_runtime.h>
#include <cuda_bf16.h>
#include <cstdint>

#define DIM     64
#define KC      8192
#define NP      32768
#define MT      64           // points per CTA
#define NT      64           // codes per tile
#define NTILES  (KC / NT)    // 128
#define GT      256
#define ROWB    208          // int8 row bytes: 192 data + 16 pad (13*16 -> conflict-free)

// int8 operands: rows of 208 bytes. A: [xh|xh|xl], B: [ch|cl|ch]
__device__ __align__(16) char d_A8[NP * ROWB];   // 6.8 MB
__device__ __align__(16) char d_B8[KC * ROWB];   // 1.7 MB
__device__ __align__(16) float d_cn[KC];
__device__ unsigned d_amax[2];
__device__ float d_sc[4];     // qa, qb, f1, f2
__device__ int2  d_cand[NP];

// SMEM: A 64x208 | B 2x 64x208 | cn 2x256 | mbar 2x8
#define S_A    0
#define S_B    13312
#define BUFSZ  13312
#define S_CN   39936
#define S_MB   40448
#define SMEM_G 40480

// ---------------------------------------------------------------------------
// helpers (all generic PTX, sm_90)
// ---------------------------------------------------------------------------
__device__ __forceinline__ uint32_t smem_u32(const void* p) {
    uint32_t a;
    asm("{ .reg .u64 t; cvta.to.shared.u64 t, %1; cvt.u32.u64 %0, t; }"
        : "=r"(a) : "l"(p));
    return a;
}
__device__ __forceinline__ void bulkcp(uint32_t dst, const void* src,
                                       uint32_t bytes, uint32_t mbar) {
    asm volatile(
        "cp.async.bulk.shared::cluster.global.mbarrier::complete_tx::bytes "
        "[%0], [%1], %2, [%3];"
        :: "r"(dst), "l"(src), "r"(bytes), "r"(mbar) : "memory");
}
#define MBAR_INIT(a, n) \
    asm volatile("mbarrier.init.shared.b64 [%0], %1;" :: "r"(a), "r"(n) : "memory")
#define MBAR_EXPECT(a, bytes) \
    asm volatile("mbarrier.arrive.expect_tx.shared.b64 _, [%0], %1;" \
                 :: "r"(a), "r"(bytes) : "memory")
__device__ __forceinline__ void mbar_wait(uint32_t mbar, uint32_t parity) {
    asm volatile(
        "{\n\t.reg .pred P;\n\t"
        "WL_%=:\n\t"
        "mbarrier.try_wait.parity.acquire.cta.shared::cta.b64 P, [%0], %1, 0x989680;\n\t"
        "@P bra.uni WD_%=;\n\t"
        "bra.uni WL_%=;\n\t"
        "WD_%=:\n\t}"
        :: "r"(mbar), "r"(parity) : "memory");
}
__device__ __forceinline__ void ldm_x4(uint32_t* r, uint32_t addr) {
    asm volatile("ldmatrix.sync.aligned.m8n8.x4.shared.b16 {%0,%1,%2,%3}, [%4];"
                 : "=r"(r[0]), "=r"(r[1]), "=r"(r[2]), "=r"(r[3]) : "r"(addr));
}
// m16n8k32 s8 IMMA; fragment layouts = b16 m16n8k16 layouts (2 int8 per b16)
__device__ __forceinline__ void mma_s8(int* d, const uint32_t* a,
                                       uint32_t b0, uint32_t b1) {
    asm volatile(
        "mma.sync.aligned.m16n8k32.row.col.s32.s8.s8.s32 "
        "{%0,%1,%2,%3}, {%4,%5,%6,%7}, {%8,%9}, {%0,%1,%2,%3};"
        : "+r"(d[0]), "+r"(d[1]), "+r"(d[2]), "+r"(d[3])
        : "r"(a[0]), "r"(a[1]), "r"(a[2]), "r"(a[3]), "r"(b0), "r"(b1));
}

// ---------------------------------------------------------------------------
// scale pipeline: reset -> absmax(ze), absmax(cb) -> mkscale
// ---------------------------------------------------------------------------
__global__ void reset_k() {
    if (threadIdx.x < 2) d_amax[threadIdx.x] = 0u;
}
__global__ void __launch_bounds__(256) absmax_k(const float* __restrict__ p,
                                                int n, int which) {
    float m = 0.f;
    for (int i = blockIdx.x * 256 + threadIdx.x; i < n; i += gridDim.x * 256)
        m = fmaxf(m, fabsf(p[i]));
#pragma unroll
    for (int o = 16; o; o >>= 1)
        m = fmaxf(m, __shfl_xor_sync(0xFFFFFFFFu, m, o));
    if ((threadIdx.x & 31) == 0)
        atomicMax(&d_amax[which], __float_as_uint(m));
}
__global__ void mkscale_k() {
    float aA = fmaxf(__uint_as_float(d_amax[0]), 1e-20f);
    float aB = fmaxf(__uint_as_float(d_amax[1]), 1e-20f);
    d_sc[0] = 32639.f / aA;
    d_sc[1] = 32639.f / aB;
    float sA = aA / 32639.f, sB = aB / 32639.f;
    d_sc[2] = -2.f * sA * sB * 65536.f;
    d_sc[3] = -2.f * sA * sB * 256.f;
}

// ---------------------------------------------------------------------------
// prep kernels
// ---------------------------------------------------------------------------
__global__ void __launch_bounds__(256) prep_cn(const float* __restrict__ cb) {
    int k = blockIdx.x * 256 + threadIdx.x;
    const float* row = cb + (size_t)k * DIM;
    float s = 0.f;
#pragma unroll
    for (int i = 0; i < DIM; i++)
        s = __fadd_rn(s, __fmul_rn(row[i], row[i]));
    d_cn[k] = s;
}

__device__ __forceinline__ void split16(float v, float q, int& hi, int& lo) {
    int x16 = __float2int_rn(v * q);
    x16 = min(max(x16, -32640), 32639);
    hi = (x16 + 128) >> 8;
    lo = x16 - (hi << 8);
}

// A rows: [xh(64) | xh(64) | xl(64) | pad16]
__global__ void __launch_bounds__(256) prep_A(const float* __restrict__ ze) {
    __shared__ float xs[DIM * 128];
    const int tid = threadIdx.x;
    const int n0  = blockIdx.x * 128;
    const int b   = n0 >> 12;
    const int hw0 = n0 & 4095;
    const float qa = d_sc[0];
    const float* zb = ze + (size_t)b * DIM * 4096 + hw0;
#pragma unroll
    for (int it = 0; it < 32; it++) {
        int e = tid + it * 256;
        int nl = e & 127, d = e >> 7;
        xs[d * 128 + nl] = zb[(size_t)d * 4096 + nl];
    }
    __syncthreads();
    uint32_t* out = (uint32_t*)d_A8 + (size_t)blockIdx.x * 128 * 52;
#pragma unroll
    for (int i = 0; i < 26; i++) {
        int e   = tid + i * 256;      // 0..6655
        int row = e / 52;
        int w   = e % 52;             // b32 word in row
        uint32_t u = 0u;
        if (w < 48) {
            int d0 = (w & 15) * 4;
            bool lo = (w >= 32);
#pragma unroll
            for (int q = 0; q < 4; q++) {
                int hi, lw;
                split16(xs[(d0 + q) * 128 + row], qa, hi, lw);
                int byte = lo ? lw : hi;
                u |= (uint32_t)(byte & 0xFF) << (8 * q);
            }
        }
        out[row * 52 + w] = u;
    }
}

// B rows: [ch(64) | cl(64) | ch(64) | pad16]
__global__ void __launch_bounds__(256) prep_B(const float* __restrict__ cb) {
    int idx = blockIdx.x * 256 + threadIdx.x;   // 0 .. KC*52-1
    int row = idx / 52;
    int w   = idx % 52;
    const float qb = d_sc[1];
    uint32_t u = 0u;
    if (w < 48) {
        int d0 = (w & 15) * 4;
        bool lo = (w >= 16 && w < 32);
#pragma unroll
        for (int q = 0; q < 4; q++) {
            int hi, lw;
            split16(cb[(size_t)row * DIM + d0 + q], qb, hi, lw);
            int byte = lo ? lw : hi;
            u |= (uint32_t)(byte & 0xFF) << (8 * q);
        }
    }
    ((uint32_t*)d_B8)[(size_t)row * 52 + w] = u;
}

// ---------------------------------------------------------------------------
// GEMM (mma.sync s8, two s32 accumulators) + top-2 epilogue
// ---------------------------------------------------------------------------
__global__ void __launch_bounds__(GT, 3) gemm_kernel() {
    extern __shared__ char smem[];
    const uint32_t sb = smem_u32(smem);
    const int tid = threadIdx.x;
    const int wid = tid >> 5;
    const int l   = tid & 31;
    const int wm  = wid & 3;          // M-warp 0..3 (16 rows each)
    const int wn  = wid >> 2;         // N-warp 0..1 (32 cols each)
    const int m0  = blockIdx.x * MT;
    const float f1 = d_sc[2];
    const float f2 = d_sc[3];

    if (tid == 0) {
        MBAR_INIT(sb + S_MB, 1);
        MBAR_INIT(sb + S_MB + 8, 1);
    }
    __syncthreads();
    if (tid == 0) {
        MBAR_EXPECT(sb + S_MB, 13312u + 13312u + 256u);
        bulkcp(sb + S_A, d_A8 + (size_t)blockIdx.x * 13312, 13312u, sb + S_MB);
        bulkcp(sb + S_B, d_B8, 13312u, sb + S_MB);
        bulkcp(sb + S_CN, (const char*)d_cn, 256u, sb + S_MB);
        MBAR_EXPECT(sb + S_MB + 8, 13568u);
        bulkcp(sb + S_B + BUFSZ, d_B8 + 13312, 13312u, sb + S_MB + 8);
        bulkcp(sb + S_CN + 256, (const char*)d_cn + 256, 256u, sb + S_MB + 8);
    }

    // ldmatrix per-thread base addresses (b16 view of int8 data)
    const uint32_t aA = sb + S_A + (wm * 16 + (l & 15)) * ROWB + (l >> 4) * 16;
    const uint32_t bRow = (uint32_t)(wn * 32 + (l & 7) + ((l >> 3) & 1) * 8);
    const uint32_t aB0 = sb + S_B + bRow * ROWB + (l >> 4) * 16;
    const uint32_t aB1 = aB0 + 16 * ROWB;

    const int cb0 = wn * 32 + 2 * (l & 3);   // epilogue column base

    // 4 trackers: s = row_half*2 + (j&1)
    float b1[4], b2[4];
    int   i1[4], i2[4];
#pragma unroll
    for (int s = 0; s < 4; s++) { b1[s] = 3.4e38f; b2[s] = 3.4e38f; i1[s] = 0; i2[s] = 0; }

#pragma unroll 1
    for (int t = 0; t < NTILES; t++) {
        const int buf = t & 1;
        const uint32_t boff = (uint32_t)buf * BUFSZ;
        mbar_wait(sb + S_MB + 8 * buf, (t >> 1) & 1);

        int acc1[4][4], acc2[4][4];
#pragma unroll
        for (int j = 0; j < 4; j++)
#pragma unroll
            for (int q = 0; q < 4; q++) { acc1[j][q] = 0; acc2[j][q] = 0; }

        // ks 0..1: xh * ch -> acc1 (weight 65536)
#pragma unroll
        for (int ks = 0; ks < 2; ks++) {
            const uint32_t koff = (uint32_t)(ks * 32);
            uint32_t ra[4], rb01[4], rb23[4];
            ldm_x4(ra,   aA + koff);
            ldm_x4(rb01, aB0 + boff + koff);
            ldm_x4(rb23, aB1 + boff + koff);
            mma_s8(acc1[0], ra, rb01[0], rb01[2]);
            mma_s8(acc1[1], ra, rb01[1], rb01[3]);
            mma_s8(acc1[2], ra, rb23[0], rb23[2]);
            mma_s8(acc1[3], ra, rb23[1], rb23[3]);
        }
        // ks 2..5: xh*cl + xl*ch -> acc2 (weight 256)
#pragma unroll
        for (int ks = 2; ks < 6; ks++) {
            const uint32_t koff = (uint32_t)(ks * 32);
            uint32_t ra[4], rb01[4], rb23[4];
            ldm_x4(ra,   aA + koff);
            ldm_x4(rb01, aB0 + boff + koff);
            ldm_x4(rb23, aB1 + boff + koff);
            mma_s8(acc2[0], ra, rb01[0], rb01[2]);
            mma_s8(acc2[1], ra, rb01[1], rb01[3]);
            mma_s8(acc2[2], ra, rb23[0], rb23[2]);
            mma_s8(acc2[3], ra, rb23[1], rb23[3]);
        }

        // hoist cn slice into regs (buffer overwritten by t+2 copy)
        const float* cnp = (const float*)(smem + S_CN + buf * 256);
        float creg[8];
#pragma unroll
        for (int j = 0; j < 4; j++) {
            creg[2 * j]     = cnp[cb0 + j * 8];
            creg[2 * j + 1] = cnp[cb0 + j * 8 + 1];
        }

        __syncthreads();                       // all warps done with buf
        if (tid == 0 && t + 2 < NTILES) {
            uint32_t mb = sb + S_MB + 8 * buf;
            MBAR_EXPECT(mb, 13568u);
            bulkcp(sb + S_B + boff, d_B8 + (size_t)(t + 2) * 13312, 13312u, mb);
            bulkcp(sb + S_CN + buf * 256, (const char*)d_cn + (size_t)(t + 2) * 256,
                   256u, mb);
        }

        // epilogue: score = nc + f1*acc1 + f2*acc2; 4 top-2 chains
        const int kb0 = t * NT + cb0;
#pragma unroll
        for (int j = 0; j < 4; j++) {
            float c0 = creg[2 * j];
            float c1 = creg[2 * j + 1];
            int kk = kb0 + j * 8;
            const int par = j & 1;
            const int s0 = par;            // row (l>>2)
            const int s1 = 2 + par;        // row (l>>2)+8
            float v0 = fmaf(f1, (float)acc1[j][0], fmaf(f2, (float)acc2[j][0], c0));
            float v1 = fmaf(f1, (float)acc1[j][1], fmaf(f2, (float)acc2[j][1], c1));
            float v2 = fmaf(f1, (float)acc1[j][2], fmaf(f2, (float)acc2[j][2], c0));
            float v3 = fmaf(f1, (float)acc1[j][3], fmaf(f2, (float)acc2[j][3], c1));
            if (v0 < b1[s0]) { b2[s0] = b1[s0]; i2[s0] = i1[s0]; b1[s0] = v0; i1[s0] = kk; }
            else if (v0 < b2[s0]) { b2[s0] = v0; i2[s0] = kk; }
            if (v1 < b1[s0]) { b2[s0] = b1[s0]; i2[s0] = i1[s0]; b1[s0] = v1; i1[s0] = kk + 1; }
            else if (v1 < b2[s0]) { b2[s0] = v1; i2[s0] = kk + 1; }
            if (v2 < b1[s1]) { b2[s1] = b1[s1]; i2[s1] = i1[s1]; b1[s1] = v2; i1[s1] = kk; }
            else if (v2 < b2[s1]) { b2[s1] = v2; i2[s1] = kk; }
            if (v3 < b1[s1]) { b2[s1] = b1[s1]; i2[s1] = i1[s1]; b1[s1] = v3; i1[s1] = kk + 1; }
            else if (v3 < b2[s1]) { b2[s1] = v3; i2[s1] = kk + 1; }
        }
    }

    // merge parity trackers -> 2 row slots (row halves)
    float m1[2], m2[2];
    int   n1[2], n2i[2];
#pragma unroll
    for (int h = 0; h < 2; h++) {
        float a1 = b1[2 * h], a2 = b2[2 * h];
        int   x1 = i1[2 * h], x2 = i2[2 * h];
        float c1v = b1[2 * h + 1], c2v = b2[2 * h + 1];
        int   y1 = i1[2 * h + 1], y2 = i2[2 * h + 1];
        if (c1v < a1) {
            float t2v = fminf(a1, c2v);
            int   t2i = (c2v < a1) ? y2 : x1;
            a2 = t2v; x2 = t2i;
            a1 = c1v; x1 = y1;
        } else if (c1v < a2) {
            a2 = c1v; x2 = y1;
        }
        m1[h] = a1; n1[h] = x1; m2[h] = a2; n2i[h] = x2;
    }

    // quad merge (lanes sharing l>>2 hold same rows)
#pragma unroll
    for (int h = 0; h < 2; h++) {
#pragma unroll
        for (int off = 1; off <= 2; off <<= 1) {
            float t1 = __shfl_xor_sync(0xFFFFFFFFu, m1[h], off);
            int   j1 = __shfl_xor_sync(0xFFFFFFFFu, n1[h], off);
            float t2 = __shfl_xor_sync(0xFFFFFFFFu, m2[h], off);
            int   j2 = __shfl_xor_sync(0xFFFFFFFFu, n2i[h], off);
            if (t1 < m1[h]) {
                float nb2 = fminf(m1[h], t2);
                int   ni2 = (t2 < m1[h]) ? j2 : n1[h];
                m1[h] = t1; n1[h] = j1; m2[h] = nb2; n2i[h] = ni2;
            } else if (t1 < m2[h]) {
                m2[h] = t1; n2i[h] = j1;
            }
        }
    }

    // cross-N-warp merge via smem (reuse B region; all B reads done)
    float4* red = (float4*)(smem + S_B);       // [64 rows][2 wn]
    if ((l & 3) == 0) {
#pragma unroll
        for (int h = 0; h < 2; h++) {
            int row = wm * 16 + h * 8 + (l >> 2);
            red[row * 2 + wn] = make_float4(m1[h], __int_as_float(n1[h]),
                                            m2[h], __int_as_float(n2i[h]));
        }
    }
    __syncthreads();
    if (tid < MT) {
        float4 A4 = red[tid * 2 + 0];
        float4 B4 = red[tid * 2 + 1];
        float s1 = A4.x, s2 = A4.z;
        int   k1 = __float_as_int(A4.y), k2 = __float_as_int(A4.w);
        float t1 = B4.x, t2 = B4.z;
        int   j1 = __float_as_int(B4.y), j2 = __float_as_int(B4.w);
        if (t1 < s1) {
            float n2v = fminf(s1, t2);
            int   n2x = (t2 < s1) ? j2 : k1;
            s1 = t1; k1 = j1; s2 = n2v; k2 = n2x;
        } else if (t1 < s2) {
            s2 = t1; k2 = j1;
        }
        d_cand[m0 + tid] = make_int2(k1, k2);
    }
}

// ---------------------------------------------------------------------------
// finalize: exact rescore (reference-identical rounding) + gather, fused.
// ---------------------------------------------------------------------------
__global__ void __launch_bounds__(128) finalize(const float* __restrict__ ze,
                                                const float* __restrict__ cb,
                                                float* __restrict__ out) {
    __shared__ int bx[64];
    const int tid = threadIdx.x;
    const int n0  = blockIdx.x * 64;
    const int b   = n0 >> 12;
    const int hw0 = n0 & 4095;

    if (tid < 64) {
        const int n  = n0 + tid;
        const int hw = hw0 + tid;
        float x[DIM];
#pragma unroll
        for (int d = 0; d < DIM; d++)
            x[d] = ze[(size_t)(b * DIM + d) * 4096 + hw];
        float nx = 0.f;
#pragma unroll
        for (int d = 0; d < DIM; d++)
            nx = __fadd_rn(nx, __fmul_rn(x[d], x[d]));
        int2 cd = d_cand[n];
        int ka = min(cd.x, cd.y), kb = max(cd.x, cd.y);
        const float* ra = cb + (size_t)ka * DIM;
        const float* rb = cb + (size_t)kb * DIM;
        float ma = 0.f, mb = 0.f;
#pragma unroll
        for (int d = 0; d < DIM; d++) {
            ma = __fmaf_rn(x[d], ra[d], ma);
            mb = __fmaf_rn(x[d], rb[d], mb);
        }
        float d2a = __fadd_rn(__fadd_rn(nx, -__fmul_rn(2.0f, ma)), d_cn[ka]);
        float d2b = __fadd_rn(__fadd_rn(nx, -__fmul_rn(2.0f, mb)), d_cn[kb]);
        bx[tid] = (d2b < d2a) ? kb : ka;   // strict: tie -> lower index
    }
    __syncthreads();

    float* ob = out + (size_t)b * DIM * 4096 + hw0;
#pragma unroll
    for (int it = 0; it < 32; it++) {
        int e = tid + it * 128;
        int nl = e & 63, d = e >> 6;
        ob[(size_t)d * 4096 + nl] = cb[(size_t)bx[nl] * DIM + d];
    }
}

extern "C" void kernel_launch(void* const* d_in, const int* in_sizes, int n_in,
                              void* d_out, int out_size) {
    const float* ze = (const float*)d_in[0];   // [8,64,64,64] f32
    const float* cb = (const float*)d_in[1];   // [8192,64] f32
    float* out = (float*)d_out;

    cudaFuncSetAttribute(gemm_kernel, cudaFuncAttributeMaxDynamicSharedMemorySize,
                         SMEM_G);

    reset_k<<<1, 32>>>();
    absmax_k<<<192, 256>>>(ze, NP * DIM, 0);
    absmax_k<<<64, 256>>>(cb, KC * DIM, 1);
    mkscale_k<<<1, 1>>>();
    prep_cn<<<KC / 256, 256>>>(cb);
    prep_A<<<NP / 128, 256>>>(ze);
    prep_B<<<(KC * 52) / 256, 256>>>(cb);
    gemm_kernel<<<NP / MT, GT, SMEM_G>>>();
    finalize<<<NP / 64, 128>>>(ze, cb, out);
}

// round 14
// speedup vs baseline: 2.9703x; 2.9703x over previous
#include <cuda_runtime.h>
#include <cuda_fp16.h>
#include <cstdint>

#define DIM     64
#define KC      8192
#define NP      32768
#define MT      128          // points per CTA
#define NT      64           // codes per tile
#define NTILES  (KC / NT)    // 128
#define GT      256
#define SMLD    144          // row stride bytes (9*16, odd multiple -> conflict-free)

// fp16 hi-only operands, rows padded to 144 B (128 B data + 16 pad)
__device__ __align__(16) char d_A16[NP * SMLD];   // 4.7 MB
__device__ __align__(16) char d_B16[KC * SMLD];   // 1.2 MB
__device__ __align__(16) float d_cn[KC];
__device__ int4  d_cand[NP];

// SMEM: A 128x144 | B 2x 64x144 | cn 2x256 | mbar 2x8
#define S_A    0
#define S_B    18432
#define BUFSZ  9216
#define S_CN   36864
#define S_MB   37376
#define SMEM_G 37408

// ---------------------------------------------------------------------------
// helpers (all generic PTX, sm_90)
// ---------------------------------------------------------------------------
__device__ __forceinline__ uint32_t smem_u32(const void* p) {
    uint32_t a;
    asm("{ .reg .u64 t; cvta.to.shared.u64 t, %1; cvt.u32.u64 %0, t; }"
        : "=r"(a) : "l"(p));
    return a;
}
__device__ __forceinline__ void bulkcp(uint32_t dst, const void* src,
                                       uint32_t bytes, uint32_t mbar) {
    asm volatile(
        "cp.async.bulk.shared::cluster.global.mbarrier::complete_tx::bytes "
        "[%0], [%1], %2, [%3];"
        :: "r"(dst), "l"(src), "r"(bytes), "r"(mbar) : "memory");
}
#define MBAR_INIT(a, n) \
    asm volatile("mbarrier.init.shared.b64 [%0], %1;" :: "r"(a), "r"(n) : "memory")
#define MBAR_EXPECT(a, bytes) \
    asm volatile("mbarrier.arrive.expect_tx.shared.b64 _, [%0], %1;" \
                 :: "r"(a), "r"(bytes) : "memory")
__device__ __forceinline__ void mbar_wait(uint32_t mbar, uint32_t parity) {
    asm volatile(
        "{\n\t.reg .pred P;\n\t"
        "WL_%=:\n\t"
        "mbarrier.try_wait.parity.acquire.cta.shared::cta.b64 P, [%0], %1, 0x989680;\n\t"
        "@P bra.uni WD_%=;\n\t"
        "bra.uni WL_%=;\n\t"
        "WD_%=:\n\t}"
        :: "r"(mbar), "r"(parity) : "memory");
}
__device__ __forceinline__ void ldm_x4(uint32_t* r, uint32_t addr) {
    asm volatile("ldmatrix.sync.aligned.m8n8.x4.shared.b16 {%0,%1,%2,%3}, [%4];"
                 : "=r"(r[0]), "=r"(r[1]), "=r"(r[2]), "=r"(r[3]) : "r"(addr));
}
__device__ __forceinline__ void mma_f16(float* d, const uint32_t* a,
                                        uint32_t b0, uint32_t b1) {
    asm volatile(
        "mma.sync.aligned.m16n8k16.row.col.f32.f16.f16.f32 "
        "{%0,%1,%2,%3}, {%4,%5,%6,%7}, {%8,%9}, {%0,%1,%2,%3};"
        : "+f"(d[0]), "+f"(d[1]), "+f"(d[2]), "+f"(d[3])
        : "r"(a[0]), "r"(a[1]), "r"(a[2]), "r"(a[3]), "r"(b0), "r"(b1));
}

// ---------------------------------------------------------------------------
// prep kernels
// ---------------------------------------------------------------------------
__global__ void __launch_bounds__(256) prep_cn(const float* __restrict__ cb) {
    int k = blockIdx.x * 256 + threadIdx.x;
    const float* row = cb + (size_t)k * DIM;
    float s = 0.f;
#pragma unroll
    for (int i = 0; i < DIM; i++)
        s = __fadd_rn(s, __fmul_rn(row[i], row[i]));
    d_cn[k] = s;
}

__device__ __forceinline__ uint32_t pack_h2(float a, float b) {
    __half h0 = __float2half_rn(a);
    __half h1 = __float2half_rn(b);
    return (uint32_t)__half_as_ushort(h0) | ((uint32_t)__half_as_ushort(h1) << 16);
}

// A rows: 64 fp16 (128 B) + 16 B pad, per-CTA contiguous blocks
__global__ void __launch_bounds__(256) prep_A(const float* __restrict__ ze) {
    __shared__ float xs[DIM * 128];
    const int tid = threadIdx.x;
    const int n0  = blockIdx.x * 128;
    const int b   = n0 >> 12;
    const int hw0 = n0 & 4095;
    const float* zb = ze + (size_t)b * DIM * 4096 + hw0;
#pragma unroll
    for (int it = 0; it < 32; it++) {
        int e = tid + it * 256;
        int nl = e & 127, d = e >> 7;
        xs[d * 128 + nl] = zb[(size_t)d * 4096 + nl];
    }
    __syncthreads();
    uint32_t* out = (uint32_t*)d_A16 + (size_t)blockIdx.x * 128 * 36;
#pragma unroll
    for (int i = 0; i < 18; i++) {
        int e   = tid + i * 256;      // 0..4607
        int row = e / 36;
        int w   = e % 36;             // b32 word (2 fp16)
        uint32_t u = 0u;
        if (w < 32) {
            int d0 = w * 2;
            u = pack_h2(xs[d0 * 128 + row], xs[(d0 + 1) * 128 + row]);
        }
        out[row * 36 + w] = u;
    }
}

// B rows: 64 fp16 + pad
__global__ void __launch_bounds__(256) prep_B(const float* __restrict__ cb) {
    int idx = blockIdx.x * 256 + threadIdx.x;   // 0 .. KC*36-1
    int row = idx / 36;
    int w   = idx % 36;
    uint32_t u = 0u;
    if (w < 32) {
        int d0 = w * 2;
        u = pack_h2(cb[(size_t)row * DIM + d0], cb[(size_t)row * DIM + d0 + 1]);
    }
    ((uint32_t*)d_B16)[(size_t)row * 36 + w] = u;
}

// ---------------------------------------------------------------------------
// GEMM (mma.sync f16, K=64) + 8-tracker top-2-per-parity epilogue
// ---------------------------------------------------------------------------
__global__ void __launch_bounds__(GT, 2) gemm_kernel() {
    extern __shared__ char smem[];
    const uint32_t sb = smem_u32(smem);
    const int tid = threadIdx.x;
    const int wid = tid >> 5;
    const int l   = tid & 31;
    const int wm  = wid & 3;          // M-warp 0..3 (32 rows each)
    const int wn  = wid >> 2;         // N-warp 0..1 (32 cols each)
    const int m0  = blockIdx.x * MT;

    if (tid == 0) {
        MBAR_INIT(sb + S_MB, 1);
        MBAR_INIT(sb + S_MB + 8, 1);
    }
    __syncthreads();
    if (tid == 0) {
        // stage 0: A + B0 + cn0
        MBAR_EXPECT(sb + S_MB, 18432u + 9216u + 256u);
        bulkcp(sb + S_A, d_A16 + (size_t)blockIdx.x * 18432, 18432u, sb + S_MB);
        bulkcp(sb + S_B, d_B16, 9216u, sb + S_MB);
        bulkcp(sb + S_CN, (const char*)d_cn, 256u, sb + S_MB);
        // stage 1: B1 + cn1
        MBAR_EXPECT(sb + S_MB + 8, 9472u);
        bulkcp(sb + S_B + BUFSZ, d_B16 + 9216, 9216u, sb + S_MB + 8);
        bulkcp(sb + S_CN + 256, (const char*)d_cn + 256, 256u, sb + S_MB + 8);
    }

    // ldmatrix per-thread base addresses
    const uint32_t aA0 = sb + S_A + (wm * 32 + (l & 15)) * SMLD + (l >> 4) * 16;
    const uint32_t aA1 = aA0 + 16 * SMLD;
    const uint32_t bRow = (uint32_t)(wn * 32 + (l & 7) + ((l >> 3) & 1) * 8);
    const uint32_t aB0 = sb + S_B + bRow * SMLD + (l >> 4) * 16;
    const uint32_t aB1 = aB0 + 16 * SMLD;

    const int cb0 = wn * 32 + 2 * (l & 3);   // epilogue column base

    // 8 trackers: index = row-slot (mt*2+half)*2 + (j&1)
    float b1[8], b2[8];
    int   i1[8], i2[8];
#pragma unroll
    for (int s = 0; s < 8; s++) { b1[s] = 3.4e38f; b2[s] = 3.4e38f; i1[s] = 0; i2[s] = 0; }

#pragma unroll 1
    for (int t = 0; t < NTILES; t++) {
        const int buf = t & 1;
        const uint32_t boff = (uint32_t)buf * BUFSZ;
        mbar_wait(sb + S_MB + 8 * buf, (t >> 1) & 1);

        float acc[2][4][4];
#pragma unroll
        for (int mt = 0; mt < 2; mt++)
#pragma unroll
            for (int j = 0; j < 4; j++)
#pragma unroll
                for (int q = 0; q < 4; q++) acc[mt][j][q] = 0.f;

#pragma unroll
        for (int ks = 0; ks < 4; ks++) {
            const uint32_t koff = (uint32_t)(ks * 32);   // 16 fp16 = 32 B
            uint32_t ra0[4], ra1[4], rb01[4], rb23[4];
            ldm_x4(ra0,  aA0 + koff);
            ldm_x4(ra1,  aA1 + koff);
            ldm_x4(rb01, aB0 + boff + koff);
            ldm_x4(rb23, aB1 + boff + koff);
            mma_f16(acc[0][0], ra0, rb01[0], rb01[2]);
            mma_f16(acc[0][1], ra0, rb01[1], rb01[3]);
            mma_f16(acc[0][2], ra0, rb23[0], rb23[2]);
            mma_f16(acc[0][3], ra0, rb23[1], rb23[3]);
            mma_f16(acc[1][0], ra1, rb01[0], rb01[2]);
            mma_f16(acc[1][1], ra1, rb01[1], rb01[3]);
            mma_f16(acc[1][2], ra1, rb23[0], rb23[2]);
            mma_f16(acc[1][3], ra1, rb23[1], rb23[3]);
        }

        // hoist cn slice into regs (buffer overwritten by t+2 copy)
        const float* cnp = (const float*)(smem + S_CN + buf * 256);
        float creg[8];
#pragma unroll
        for (int j = 0; j < 4; j++) {
            creg[2 * j]     = cnp[cb0 + j * 8];
            creg[2 * j + 1] = cnp[cb0 + j * 8 + 1];
        }

        __syncthreads();                       // all warps done with buf
        if (tid == 0 && t + 2 < NTILES) {
            uint32_t mb = sb + S_MB + 8 * buf;
            MBAR_EXPECT(mb, 9472u);
            bulkcp(sb + S_B + boff, d_B16 + (size_t)(t + 2) * 9216, 9216u, mb);
            bulkcp(sb + S_CN + buf * 256, (const char*)d_cn + (size_t)(t + 2) * 256,
                   256u, mb);
        }

        // epilogue: score = nc - 2*m; 8 independent top-2 chains
        const int kb0 = t * NT + cb0;
#pragma unroll
        for (int j = 0; j < 4; j++) {
            float c0 = creg[2 * j];
            float c1 = creg[2 * j + 1];
            int kk = kb0 + j * 8;
            const int par = j & 1;
#pragma unroll
            for (int mt = 0; mt < 2; mt++) {
                const int s0 = (mt * 2) * 2 + par;
                const int s1 = (mt * 2 + 1) * 2 + par;
                float v0 = fmaf(-2.f, acc[mt][j][0], c0);
                float v1 = fmaf(-2.f, acc[mt][j][1], c1);
                float v2 = fmaf(-2.f, acc[mt][j][2], c0);
                float v3 = fmaf(-2.f, acc[mt][j][3], c1);
                if (v0 < b1[s0]) { b2[s0] = b1[s0]; i2[s0] = i1[s0]; b1[s0] = v0; i1[s0] = kk; }
                else if (v0 < b2[s0]) { b2[s0] = v0; i2[s0] = kk; }
                if (v1 < b1[s0]) { b2[s0] = b1[s0]; i2[s0] = i1[s0]; b1[s0] = v1; i1[s0] = kk + 1; }
                else if (v1 < b2[s0]) { b2[s0] = v1; i2[s0] = kk + 1; }
                if (v2 < b1[s1]) { b2[s1] = b1[s1]; i2[s1] = i1[s1]; b1[s1] = v2; i1[s1] = kk; }
                else if (v2 < b2[s1]) { b2[s1] = v2; i2[s1] = kk; }
                if (v3 < b1[s1]) { b2[s1] = b1[s1]; i2[s1] = i1[s1]; b1[s1] = v3; i1[s1] = kk + 1; }
                else if (v3 < b2[s1]) { b2[s1] = v3; i2[s1] = kk + 1; }
            }
        }
    }

    // quad merge per (row-slot, parity): keep top-2 of each parity class
#pragma unroll
    for (int s = 0; s < 8; s++) {
#pragma unroll
        for (int off = 1; off <= 2; off <<= 1) {
            float t1 = __shfl_xor_sync(0xFFFFFFFFu, b1[s], off);
            int   j1 = __shfl_xor_sync(0xFFFFFFFFu, i1[s], off);
            float t2 = __shfl_xor_sync(0xFFFFFFFFu, b2[s], off);
            int   j2 = __shfl_xor_sync(0xFFFFFFFFu, i2[s], off);
            if (t1 < b1[s]) {
                float nb2 = fminf(b1[s], t2);
                int   ni2 = (t2 < b1[s]) ? j2 : i1[s];
                b1[s] = t1; i1[s] = j1; b2[s] = nb2; i2[s] = ni2;
            } else if (t1 < b2[s]) {
                b2[s] = t1; i2[s] = j1;
            }
        }
    }

    // cross-N-warp merge via smem: red[row][wn][par] (B region, reads done)
    float4* red = (float4*)(smem + S_B);       // [128 rows][2 wn][2 par]
    if ((l & 3) == 0) {
#pragma unroll
        for (int rs = 0; rs < 4; rs++) {
#pragma unroll
            for (int par = 0; par < 2; par++) {
                int s = rs * 2 + par;
                int row = wm * 32 + (rs >> 1) * 16 + (rs & 1) * 8 + (l >> 2);
                red[(row * 2 + wn) * 2 + par] =
                    make_float4(b1[s], __int_as_float(i1[s]),
                                b2[s], __int_as_float(i2[s]));
            }
        }
    }
    __syncthreads();
    if (tid < MT) {
        int kcand[4];
#pragma unroll
        for (int par = 0; par < 2; par++) {
            float4 A4 = red[(tid * 2 + 0) * 2 + par];
            float4 B4 = red[(tid * 2 + 1) * 2 + par];
            float s1 = A4.x, s2 = A4.z;
            int   k1 = __float_as_int(A4.y), k2 = __float_as_int(A4.w);
            float t1 = B4.x, t2 = B4.z;
            int   j1 = __float_as_int(B4.y), j2 = __float_as_int(B4.w);
            if (t1 < s1) {
                float n2v = fminf(s1, t2);
                int   n2x = (t2 < s1) ? j2 : k1;
                s1 = t1; k1 = j1; s2 = n2v; k2 = n2x;
            } else if (t1 < s2) {
                s2 = t1; k2 = j1;
            }
            kcand[par * 2]     = k1;
            kcand[par * 2 + 1] = k2;
        }
        d_cand[m0 + tid] = make_int4(kcand[0], kcand[1], kcand[2], kcand[3]);
    }
}

// ---------------------------------------------------------------------------
// finalize: exact rescore of 4 candidates (reference rounding) + gather
// ---------------------------------------------------------------------------
__global__ void __launch_bounds__(128) finalize(const float* __restrict__ ze,
                                                const float* __restrict__ cb,
                                                float* __restrict__ out) {
    __shared__ int bx[64];
    const int tid = threadIdx.x;
    const int n0  = blockIdx.x * 64;
    const int b   = n0 >> 12;
    const int hw0 = n0 & 4095;

    if (tid < 64) {
        const int n  = n0 + tid;
        const int hw = hw0 + tid;
        float x[DIM];
#pragma unroll
        for (int d = 0; d < DIM; d++)
            x[d] = ze[(size_t)(b * DIM + d) * 4096 + hw];
        float nx = 0.f;
#pragma unroll
        for (int d = 0; d < DIM; d++)
            nx = __fadd_rn(nx, __fmul_rn(x[d], x[d]));
        int4 cd = d_cand[n];
        int cands[4] = {cd.x, cd.y, cd.z, cd.w};
        float bd = 3.4e38f;
        int   bi = 0x7fffffff;
#pragma unroll
        for (int q = 0; q < 4; q++) {
            int k = cands[q];
            const float* r = cb + (size_t)k * DIM;
            float m = 0.f;
#pragma unroll
            for (int d = 0; d < DIM; d++)
                m = __fmaf_rn(x[d], r[d], m);
            float d2 = __fadd_rn(__fadd_rn(nx, -__fmul_rn(2.0f, m)), d_cn[k]);
            if (d2 < bd || (d2 == bd && k < bi)) { bd = d2; bi = k; }
        }
        bx[tid] = bi;
    }
    __syncthreads();

    float* ob = out + (size_t)b * DIM * 4096 + hw0;
#pragma unroll
    for (int it = 0; it < 32; it++) {
        int e = tid + it * 128;
        int nl = e & 63, d = e >> 6;
        ob[(size_t)d * 4096 + nl] = cb[(size_t)bx[nl] * DIM + d];
    }
}

extern "C" void kernel_launch(void* const* d_in, const int* in_sizes, int n_in,
                              void* d_out, int out_size) {
    const float* ze = (const float*)d_in[0];   // [8,64,64,64] f32
    const float* cb = (const float*)d_in[1];   // [8192,64] f32
    float* out = (float*)d_out;

    cudaFuncSetAttribute(gemm_kernel, cudaFuncAttributeMaxDynamicSharedMemorySize,
                         SMEM_G);

    prep_cn<<<KC / 256, 256>>>(cb);
    prep_A<<<NP / 128, 256>>>(ze);
    prep_B<<<(KC * 36) / 256, 256>>>(cb);
    gemm_kernel<<<NP / MT, GT, SMEM_G>>>();
    finalize<<<NP / 64, 128>>>(ze, cb, out);
}

// round 15
// speedup vs baseline: 3.4782x; 1.1710x over previous
#include <cuda_runtime.h>
#include <cuda_fp16.h>
#include <cstdint>

#define DIM     64
#define KC      8192
#define NP      32768
#define MT      128          // points per CTA
#define NT      64           // codes per tile
#define NTILES  (KC / NT)    // 128
#define GT      256
#define SMLD    176          // row stride bytes (11*16, odd -> conflict-free ldsm)
#define ROWW    44           // u32 words per row

// fp16 rows: [x(64) | 1,1,0.. (16)] for A; [c(64) | -nc/2 hi,lo, 0.. (16)] for B
__device__ __align__(16) char d_A16[NP * SMLD];   // 5.8 MB
__device__ __align__(16) char d_B16[KC * SMLD];   // 1.4 MB
__device__ __align__(16) float d_cn[KC];
__device__ int4  d_cand[NP];

// SMEM: A 128x176 | B 2x 64x176 | mbar 2x8
#define S_A    0
#define S_B    22528
#define BUFSZ  11264
#define S_MB   45056
#define SMEM_G 45088

// ---------------------------------------------------------------------------
// helpers (all generic PTX, sm_90)
// ---------------------------------------------------------------------------
__device__ __forceinline__ uint32_t smem_u32(const void* p) {
    uint32_t a;
    asm("{ .reg .u64 t; cvta.to.shared.u64 t, %1; cvt.u32.u64 %0, t; }"
        : "=r"(a) : "l"(p));
    return a;
}
__device__ __forceinline__ void bulkcp(uint32_t dst, const void* src,
                                       uint32_t bytes, uint32_t mbar) {
    asm volatile(
        "cp.async.bulk.shared::cluster.global.mbarrier::complete_tx::bytes "
        "[%0], [%1], %2, [%3];"
        :: "r"(dst), "l"(src), "r"(bytes), "r"(mbar) : "memory");
}
#define MBAR_INIT(a, n) \
    asm volatile("mbarrier.init.shared.b64 [%0], %1;" :: "r"(a), "r"(n) : "memory")
#define MBAR_EXPECT(a, bytes) \
    asm volatile("mbarrier.arrive.expect_tx.shared.b64 _, [%0], %1;" \
                 :: "r"(a), "r"(bytes) : "memory")
__device__ __forceinline__ void mbar_wait(uint32_t mbar, uint32_t parity) {
    asm volatile(
        "{\n\t.reg .pred P;\n\t"
        "WL_%=:\n\t"
        "mbarrier.try_wait.parity.acquire.cta.shared::cta.b64 P, [%0], %1, 0x989680;\n\t"
        "@P bra.uni WD_%=;\n\t"
        "bra.uni WL_%=;\n\t"
        "WD_%=:\n\t}"
        :: "r"(mbar), "r"(parity) : "memory");
}
__device__ __forceinline__ void ldm_x4(uint32_t* r, uint32_t addr) {
    asm volatile("ldmatrix.sync.aligned.m8n8.x4.shared.b16 {%0,%1,%2,%3}, [%4];"
                 : "=r"(r[0]), "=r"(r[1]), "=r"(r[2]), "=r"(r[3]) : "r"(addr));
}
__device__ __forceinline__ void mma_f16(float* d, const uint32_t* a,
                                        uint32_t b0, uint32_t b1) {
    asm volatile(
        "mma.sync.aligned.m16n8k16.row.col.f32.f16.f16.f32 "
        "{%0,%1,%2,%3}, {%4,%5,%6,%7}, {%8,%9}, {%0,%1,%2,%3};"
        : "+f"(d[0]), "+f"(d[1]), "+f"(d[2]), "+f"(d[3])
        : "r"(a[0]), "r"(a[1]), "r"(a[2]), "r"(a[3]), "r"(b0), "r"(b1));
}

// ---------------------------------------------------------------------------
// prep kernels
// ---------------------------------------------------------------------------
__global__ void __launch_bounds__(256) prep_cn(const float* __restrict__ cb) {
    int k = blockIdx.x * 256 + threadIdx.x;
    const float* row = cb + (size_t)k * DIM;
    float s = 0.f;
#pragma unroll
    for (int i = 0; i < DIM; i++)
        s = __fadd_rn(s, __fmul_rn(row[i], row[i]));
    d_cn[k] = s;
}

__device__ __forceinline__ uint32_t pack_h2(float a, float b) {
    __half h0 = __float2half_rn(a);
    __half h1 = __float2half_rn(b);
    return (uint32_t)__half_as_ushort(h0) | ((uint32_t)__half_as_ushort(h1) << 16);
}

// A rows: 64 fp16 x | (1,1) | zeros ; per-CTA contiguous 176B rows
__global__ void __launch_bounds__(256) prep_A(const float* __restrict__ ze) {
    __shared__ float xs[DIM * 128];
    const int tid = threadIdx.x;
    const int n0  = blockIdx.x * 128;
    const int b   = n0 >> 12;
    const int hw0 = n0 & 4095;
    const float* zb = ze + (size_t)b * DIM * 4096 + hw0;
#pragma unroll
    for (int it = 0; it < 32; it++) {
        int e = tid + it * 256;
        int nl = e & 127, d = e >> 7;
        xs[d * 128 + nl] = zb[(size_t)d * 4096 + nl];
    }
    __syncthreads();
    uint32_t* out = (uint32_t*)d_A16 + (size_t)blockIdx.x * 128 * ROWW;
#pragma unroll
    for (int i = 0; i < 22; i++) {
        int e   = tid + i * 256;      // 0..5631
        int row = e / ROWW;
        int w   = e % ROWW;
        uint32_t u = 0u;
        if (w < 32) {
            int d0 = w * 2;
            u = pack_h2(xs[d0 * 128 + row], xs[(d0 + 1) * 128 + row]);
        } else if (w == 32) {
            u = 0x3C003C00u;          // (1.0h, 1.0h)
        }
        out[row * ROWW + w] = u;
    }
}

// B rows: 64 fp16 c | (-nc/2 hi, lo) | zeros
__global__ void __launch_bounds__(256) prep_B(const float* __restrict__ cb) {
    int idx = blockIdx.x * 256 + threadIdx.x;   // 0 .. KC*ROWW-1
    int row = idx / ROWW;
    int w   = idx % ROWW;
    uint32_t u = 0u;
    if (w < 32) {
        int d0 = w * 2;
        u = pack_h2(cb[(size_t)row * DIM + d0], cb[(size_t)row * DIM + d0 + 1]);
    } else if (w == 32) {
        float v = -0.5f * d_cn[row];
        __half hh = __float2half_rn(v);
        __half hl = __float2half_rn(v - __half2float(hh));
        u = (uint32_t)__half_as_ushort(hh) | ((uint32_t)__half_as_ushort(hl) << 16);
    }
    ((uint32_t*)d_B16)[(size_t)row * ROWW + w] = u;
}

// ---------------------------------------------------------------------------
// GEMM (mma.sync f16, K=80, nc folded) + pair-tournament top-2 epilogue
// ---------------------------------------------------------------------------
__global__ void __launch_bounds__(GT, 2) gemm_kernel() {
    extern __shared__ char smem[];
    const uint32_t sb = smem_u32(smem);
    const int tid = threadIdx.x;
    const int wid = tid >> 5;
    const int l   = tid & 31;
    const int wm  = wid & 3;          // M-warp 0..3 (32 rows each)
    const int wn  = wid >> 2;         // N-warp 0..1 (32 cols each)
    const int m0  = blockIdx.x * MT;

    if (tid == 0) {
        MBAR_INIT(sb + S_MB, 1);
        MBAR_INIT(sb + S_MB + 8, 1);
    }
    __syncthreads();
    if (tid == 0) {
        MBAR_EXPECT(sb + S_MB, 22528u + 11264u);
        bulkcp(sb + S_A, d_A16 + (size_t)blockIdx.x * 22528, 22528u, sb + S_MB);
        bulkcp(sb + S_B, d_B16, 11264u, sb + S_MB);
        MBAR_EXPECT(sb + S_MB + 8, 11264u);
        bulkcp(sb + S_B + BUFSZ, d_B16 + 11264, 11264u, sb + S_MB + 8);
    }

    // ldmatrix per-thread base addresses
    const uint32_t aA0 = sb + S_A + (wm * 32 + (l & 15)) * SMLD + (l >> 4) * 16;
    const uint32_t aA1 = aA0 + 16 * SMLD;
    const uint32_t bRow = (uint32_t)(wn * 32 + (l & 7) + ((l >> 3) & 1) * 8);
    const uint32_t aB0 = sb + S_B + bRow * SMLD + (l >> 4) * 16;
    const uint32_t aB1 = aB0 + 16 * SMLD;

    const int cb0 = wn * 32 + 2 * (l & 3);   // epilogue column base

    // 8 MAX trackers: index = row-slot (mt*2+half)*2 + (j&1)
    float b1[8], b2[8];
    int   i1[8], i2[8];
#pragma unroll
    for (int s = 0; s < 8; s++) { b1[s] = -3.4e38f; b2[s] = -3.4e38f; i1[s] = 0; i2[s] = 0; }

#pragma unroll 1
    for (int t = 0; t < NTILES; t++) {
        const int buf = t & 1;
        const uint32_t boff = (uint32_t)buf * BUFSZ;
        mbar_wait(sb + S_MB + 8 * buf, (t >> 1) & 1);

        float acc[2][4][4];
#pragma unroll
        for (int mt = 0; mt < 2; mt++)
#pragma unroll
            for (int j = 0; j < 4; j++)
#pragma unroll
                for (int q = 0; q < 4; q++) acc[mt][j][q] = 0.f;

#pragma unroll
        for (int ks = 0; ks < 5; ks++) {
            const uint32_t koff = (uint32_t)(ks * 32);   // 16 fp16 = 32 B
            uint32_t ra0[4], ra1[4], rb01[4], rb23[4];
            ldm_x4(ra0,  aA0 + koff);
            ldm_x4(ra1,  aA1 + koff);
            ldm_x4(rb01, aB0 + boff + koff);
            ldm_x4(rb23, aB1 + boff + koff);
            mma_f16(acc[0][0], ra0, rb01[0], rb01[2]);
            mma_f16(acc[0][1], ra0, rb01[1], rb01[3]);
            mma_f16(acc[0][2], ra0, rb23[0], rb23[2]);
            mma_f16(acc[0][3], ra0, rb23[1], rb23[3]);
            mma_f16(acc[1][0], ra1, rb01[0], rb01[2]);
            mma_f16(acc[1][1], ra1, rb01[1], rb01[3]);
            mma_f16(acc[1][2], ra1, rb23[0], rb23[2]);
            mma_f16(acc[1][3], ra1, rb23[1], rb23[3]);
        }

        __syncthreads();                       // all warps done reading buf
        if (tid == 0 && t + 2 < NTILES) {
            uint32_t mb = sb + S_MB + 8 * buf;
            MBAR_EXPECT(mb, 11264u);
            bulkcp(sb + S_B + boff, d_B16 + (size_t)(t + 2) * 11264, 11264u, mb);
        }

        // epilogue: score = acc (argmax of m - nc/2); adjacent-pair tournament,
        // then one top-2 insert per pair. Ties keep lower index everywhere.
        const int kb0 = t * NT + cb0;
#pragma unroll
        for (int j = 0; j < 4; j++) {
            int kk = kb0 + j * 8;
            const int par = j & 1;
#pragma unroll
            for (int mt = 0; mt < 2; mt++) {
                const int s0 = (mt * 2) * 2 + par;
                const int s1 = (mt * 2 + 1) * 2 + par;
                float v0 = acc[mt][j][0], v1 = acc[mt][j][1];
                float v2 = acc[mt][j][2], v3 = acc[mt][j][3];
                float p0 = fmaxf(v0, v1);
                int   q0 = (v1 > v0) ? kk + 1 : kk;
                float p1 = fmaxf(v2, v3);
                int   q1 = (v3 > v2) ? kk + 1 : kk;
                if (p0 > b1[s0]) { b2[s0] = b1[s0]; i2[s0] = i1[s0]; b1[s0] = p0; i1[s0] = q0; }
                else if (p0 > b2[s0]) { b2[s0] = p0; i2[s0] = q0; }
                if (p1 > b1[s1]) { b2[s1] = b1[s1]; i2[s1] = i1[s1]; b1[s1] = p1; i1[s1] = q1; }
                else if (p1 > b2[s1]) { b2[s1] = p1; i2[s1] = q1; }
            }
        }
    }

    // quad merge per (row-slot, parity): keep top-2 of each parity class
#pragma unroll
    for (int s = 0; s < 8; s++) {
#pragma unroll
        for (int off = 1; off <= 2; off <<= 1) {
            float t1 = __shfl_xor_sync(0xFFFFFFFFu, b1[s], off);
            int   j1 = __shfl_xor_sync(0xFFFFFFFFu, i1[s], off);
            float t2 = __shfl_xor_sync(0xFFFFFFFFu, b2[s], off);
            int   j2 = __shfl_xor_sync(0xFFFFFFFFu, i2[s], off);
            if (t1 > b1[s]) {
                float nb2 = fmaxf(b1[s], t2);
                int   ni2 = (t2 > b1[s]) ? j2 : i1[s];
                b1[s] = t1; i1[s] = j1; b2[s] = nb2; i2[s] = ni2;
            } else if (t1 > b2[s]) {
                b2[s] = t1; i2[s] = j1;
            }
        }
    }

    // cross-N-warp merge via smem: red[row][wn][par] (B region, reads done)
    float4* red = (float4*)(smem + S_B);       // [128 rows][2 wn][2 par]
    if ((l & 3) == 0) {
#pragma unroll
        for (int rs = 0; rs < 4; rs++) {
#pragma unroll
            for (int par = 0; par < 2; par++) {
                int s = rs * 2 + par;
                int row = wm * 32 + (rs >> 1) * 16 + (rs & 1) * 8 + (l >> 2);
                red[(row * 2 + wn) * 2 + par] =
                    make_float4(b1[s], __int_as_float(i1[s]),
                                b2[s], __int_as_float(i2[s]));
            }
        }
    }
    __syncthreads();
    if (tid < MT) {
        int kcand[4];
#pragma unroll
        for (int par = 0; par < 2; par++) {
            float4 A4 = red[(tid * 2 + 0) * 2 + par];
            float4 B4 = red[(tid * 2 + 1) * 2 + par];
            float s1 = A4.x, s2 = A4.z;
            int   k1 = __float_as_int(A4.y), k2 = __float_as_int(A4.w);
            float t1 = B4.x, t2 = B4.z;
            int   j1 = __float_as_int(B4.y), j2 = __float_as_int(B4.w);
            if (t1 > s1) {
                float n2v = fmaxf(s1, t2);
                int   n2x = (t2 > s1) ? j2 : k1;
                s1 = t1; k1 = j1; s2 = n2v; k2 = n2x;
            } else if (t1 > s2) {
                s2 = t1; k2 = j1;
            }
            kcand[par * 2]     = k1;
            kcand[par * 2 + 1] = k2;
        }
        d_cand[m0 + tid] = make_int4(kcand[0], kcand[1], kcand[2], kcand[3]);
    }
}

// ---------------------------------------------------------------------------
// finalize: exact rescore of 4 candidates (reference rounding) + gather
// ---------------------------------------------------------------------------
__global__ void __launch_bounds__(128) finalize(const float* __restrict__ ze,
                                                const float* __restrict__ cb,
                                                float* __restrict__ out) {
    __shared__ int bx[64];
    const int tid = threadIdx.x;
    const int n0  = blockIdx.x * 64;
    const int b   = n0 >> 12;
    const int hw0 = n0 & 4095;

    if (tid < 64) {
        const int n  = n0 + tid;
        const int hw = hw0 + tid;
        float x[DIM];
#pragma unroll
        for (int d = 0; d < DIM; d++)
            x[d] = ze[(size_t)(b * DIM + d) * 4096 + hw];
        float nx = 0.f;
#pragma unroll
        for (int d = 0; d < DIM; d++)
            nx = __fadd_rn(nx, __fmul_rn(x[d], x[d]));
        int4 cd = d_cand[n];
        int cands[4] = {cd.x, cd.y, cd.z, cd.w};
        float bd = 3.4e38f;
        int   bi = 0x7fffffff;
#pragma unroll
        for (int q = 0; q < 4; q++) {
            int k = cands[q];
            const float* r = cb + (size_t)k * DIM;
            float m = 0.f;
#pragma unroll
            for (int d = 0; d < DIM; d++)
                m = __fmaf_rn(x[d], r[d], m);
            float d2 = __fadd_rn(__fadd_rn(nx, -__fmul_rn(2.0f, m)), d_cn[k]);
            if (d2 < bd || (d2 == bd && k < bi)) { bd = d2; bi = k; }
        }
        bx[tid] = bi;
    }
    __syncthreads();

    float* ob = out + (size_t)b * DIM * 4096 + hw0;
#pragma unroll
    for (int it = 0; it < 32; it++) {
        int e = tid + it * 128;
        int nl = e & 63, d = e >> 6;
        ob[(size_t)d * 4096 + nl] = cb[(size_t)bx[nl] * DIM + d];
    }
}

extern "C" void kernel_launch(void* const* d_in, const int* in_sizes, int n_in,
                              void* d_out, int out_size) {
    const float* ze = (const float*)d_in[0];   // [8,64,64,64] f32
    const float* cb = (const float*)d_in[1];   // [8192,64] f32
    float* out = (float*)d_out;

    cudaFuncSetAttribute(gemm_kernel, cudaFuncAttributeMaxDynamicSharedMemorySize,
                         SMEM_G);

    prep_cn<<<KC / 256, 256>>>(cb);
    prep_A<<<NP / 128, 256>>>(ze);
    prep_B<<<(KC * ROWW) / 256, 256>>>(cb);
    gemm_kernel<<<NP / MT, GT, SMEM_G>>>();
    finalize<<<NP / 64, 128>>>(ze, cb, out);
}

// round 16
// speedup vs baseline: 3.5817x; 1.0298x over previous
#include <cuda_runtime.h>
#include <cuda_fp16.h>
#include <cstdint>

#define DIM     64
#define KC      8192
#define NP      32768
#define MT      128          // points per CTA
#define NT      64           // codes per tile
#define NTILES  (KC / NT)    // 128
#define GT      512
#define SMLD    176          // row stride bytes (11*16, odd -> conflict-free ldsm)
#define ROWW    44           // u32 words per row

// fp16 rows: [x(64) | 1,1,0.. (16)] for A; [c(64) | -nc/2 hi,lo, 0.. (16)] for B
__device__ __align__(16) char d_A16[NP * SMLD];   // 5.8 MB
__device__ __align__(16) char d_B16[KC * SMLD];   // 1.4 MB
__device__ __align__(16) float d_cn[KC];
__device__ int2  d_cand[NP];

// SMEM: A 128x176 | B 2x 64x176 | mbar 2x8
#define S_A    0
#define S_B    22528
#define BUFSZ  11264
#define S_MB   45056
#define SMEM_G 45088

// ---------------------------------------------------------------------------
// helpers (all generic PTX, sm_90)
// ---------------------------------------------------------------------------
__device__ __forceinline__ uint32_t smem_u32(const void* p) {
    uint32_t a;
    asm("{ .reg .u64 t; cvta.to.shared.u64 t, %1; cvt.u32.u64 %0, t; }"
        : "=r"(a) : "l"(p));
    return a;
}
__device__ __forceinline__ void bulkcp(uint32_t dst, const void* src,
                                       uint32_t bytes, uint32_t mbar) {
    asm volatile(
        "cp.async.bulk.shared::cluster.global.mbarrier::complete_tx::bytes "
        "[%0], [%1], %2, [%3];"
        :: "r"(dst), "l"(src), "r"(bytes), "r"(mbar) : "memory");
}
#define MBAR_INIT(a, n) \
    asm volatile("mbarrier.init.shared.b64 [%0], %1;" :: "r"(a), "r"(n) : "memory")
#define MBAR_EXPECT(a, bytes) \
    asm volatile("mbarrier.arrive.expect_tx.shared.b64 _, [%0], %1;" \
                 :: "r"(a), "r"(bytes) : "memory")
__device__ __forceinline__ void mbar_wait(uint32_t mbar, uint32_t parity) {
    asm volatile(
        "{\n\t.reg .pred P;\n\t"
        "WL_%=:\n\t"
        "mbarrier.try_wait.parity.acquire.cta.shared::cta.b64 P, [%0], %1, 0x989680;\n\t"
        "@P bra.uni WD_%=;\n\t"
        "bra.uni WL_%=;\n\t"
        "WD_%=:\n\t}"
        :: "r"(mbar), "r"(parity) : "memory");
}
__device__ __forceinline__ void ldm_x4(uint32_t* r, uint32_t addr) {
    asm volatile("ldmatrix.sync.aligned.m8n8.x4.shared.b16 {%0,%1,%2,%3}, [%4];"
                 : "=r"(r[0]), "=r"(r[1]), "=r"(r[2]), "=r"(r[3]) : "r"(addr));
}
__device__ __forceinline__ void mma_f16(float* d, const uint32_t* a,
                                        uint32_t b0, uint32_t b1) {
    asm volatile(
        "mma.sync.aligned.m16n8k16.row.col.f32.f16.f16.f32 "
        "{%0,%1,%2,%3}, {%4,%5,%6,%7}, {%8,%9}, {%0,%1,%2,%3};"
        : "+f"(d[0]), "+f"(d[1]), "+f"(d[2]), "+f"(d[3])
        : "r"(a[0]), "r"(a[1]), "r"(a[2]), "r"(a[3]), "r"(b0), "r"(b1));
}

// ---------------------------------------------------------------------------
// prep kernels
// ---------------------------------------------------------------------------
__global__ void __launch_bounds__(256) prep_cn(const float* __restrict__ cb) {
    int k = blockIdx.x * 256 + threadIdx.x;
    const float* row = cb + (size_t)k * DIM;
    float s = 0.f;
#pragma unroll
    for (int i = 0; i < DIM; i++)
        s = __fadd_rn(s, __fmul_rn(row[i], row[i]));
    d_cn[k] = s;
}

__device__ __forceinline__ uint32_t pack_h2(float a, float b) {
    __half h0 = __float2half_rn(a);
    __half h1 = __float2half_rn(b);
    return (uint32_t)__half_as_ushort(h0) | ((uint32_t)__half_as_ushort(h1) << 16);
}

// A rows: 64 fp16 x | (1,1) | zeros ; per-CTA contiguous 176B rows
__global__ void __launch_bounds__(256) prep_A(const float* __restrict__ ze) {
    __shared__ float xs[DIM * 128];
    const int tid = threadIdx.x;
    const int n0  = blockIdx.x * 128;
    const int b   = n0 >> 12;
    const int hw0 = n0 & 4095;
    const float* zb = ze + (size_t)b * DIM * 4096 + hw0;
#pragma unroll
    for (int it = 0; it < 32; it++) {
        int e = tid + it * 256;
        int nl = e & 127, d = e >> 7;
        xs[d * 128 + nl] = zb[(size_t)d * 4096 + nl];
    }
    __syncthreads();
    uint32_t* out = (uint32_t*)d_A16 + (size_t)blockIdx.x * 128 * ROWW;
#pragma unroll
    for (int i = 0; i < 22; i++) {
        int e   = tid + i * 256;      // 0..5631
        int row = e / ROWW;
        int w   = e % ROWW;
        uint32_t u = 0u;
        if (w < 32) {
            int d0 = w * 2;
            u = pack_h2(xs[d0 * 128 + row], xs[(d0 + 1) * 128 + row]);
        } else if (w == 32) {
            u = 0x3C003C00u;          // (1.0h, 1.0h)
        }
        out[row * ROWW + w] = u;
    }
}

// B rows: 64 fp16 c | (-nc/2 hi, lo) | zeros
__global__ void __launch_bounds__(256) prep_B(const float* __restrict__ cb) {
    int idx = blockIdx.x * 256 + threadIdx.x;   // 0 .. KC*ROWW-1
    int row = idx / ROWW;
    int w   = idx % ROWW;
    uint32_t u = 0u;
    if (w < 32) {
        int d0 = w * 2;
        u = pack_h2(cb[(size_t)row * DIM + d0], cb[(size_t)row * DIM + d0 + 1]);
    } else if (w == 32) {
        float v = -0.5f * d_cn[row];
        __half hh = __float2half_rn(v);
        __half hl = __float2half_rn(v - __half2float(hh));
        u = (uint32_t)__half_as_ushort(hh) | ((uint32_t)__half_as_ushort(hl) << 16);
    }
    ((uint32_t*)d_B16)[(size_t)row * ROWW + w] = u;
}

// ---------------------------------------------------------------------------
// GEMM: 512 threads (4M x 4N warps, warp tile 32x16), K=80 nc-folded,
// pair-max tournament storing pair ids, 4 top-2 trackers.
// ---------------------------------------------------------------------------
__global__ void __launch_bounds__(GT, 2) gemm_kernel() {
    extern __shared__ char smem[];
    const uint32_t sb = smem_u32(smem);
    const int tid = threadIdx.x;
    const int wid = tid >> 5;
    const int l   = tid & 31;
    const int wm  = wid & 3;          // M-warp 0..3 (32 rows each)
    const int wn  = wid >> 2;         // N-warp 0..3 (16 cols each)
    const int m0  = blockIdx.x * MT;

    if (tid == 0) {
        MBAR_INIT(sb + S_MB, 1);
        MBAR_INIT(sb + S_MB + 8, 1);
    }
    __syncthreads();
    if (tid == 0) {
        MBAR_EXPECT(sb + S_MB, 22528u + 11264u);
        bulkcp(sb + S_A, d_A16 + (size_t)blockIdx.x * 22528, 22528u, sb + S_MB);
        bulkcp(sb + S_B, d_B16, 11264u, sb + S_MB);
        MBAR_EXPECT(sb + S_MB + 8, 11264u);
        bulkcp(sb + S_B + BUFSZ, d_B16 + 11264, 11264u, sb + S_MB + 8);
    }

    // ldmatrix per-thread base addresses
    const uint32_t aA0 = sb + S_A + (wm * 32 + (l & 15)) * SMLD + (l >> 4) * 16;
    const uint32_t aA1 = aA0 + 16 * SMLD;
    const uint32_t bRow = (uint32_t)(wn * 16 + (l & 7) + ((l >> 3) & 1) * 8);
    const uint32_t aB0 = sb + S_B + bRow * SMLD + (l >> 4) * 16;

    const int cb0 = wn * 16 + 2 * (l & 3);   // epilogue column base

    // 4 MAX trackers of pair-maxes: s = mt*2 + half; ids are PAIR ids
    float b1[4], b2[4];
    int   i1[4], i2[4];
#pragma unroll
    for (int s = 0; s < 4; s++) { b1[s] = -3.4e38f; b2[s] = -3.4e38f; i1[s] = 0; i2[s] = 0; }

#pragma unroll 1
    for (int t = 0; t < NTILES; t++) {
        const int buf = t & 1;
        const uint32_t boff = (uint32_t)buf * BUFSZ;
        mbar_wait(sb + S_MB + 8 * buf, (t >> 1) & 1);

        float acc[2][2][4];
#pragma unroll
        for (int mt = 0; mt < 2; mt++)
#pragma unroll
            for (int j = 0; j < 2; j++)
#pragma unroll
                for (int q = 0; q < 4; q++) acc[mt][j][q] = 0.f;

#pragma unroll
        for (int ks = 0; ks < 5; ks++) {
            const uint32_t koff = (uint32_t)(ks * 32);   // 16 fp16 = 32 B
            uint32_t ra0[4], ra1[4], rb[4];
            ldm_x4(ra0, aA0 + koff);
            ldm_x4(ra1, aA1 + koff);
            ldm_x4(rb,  aB0 + boff + koff);
            mma_f16(acc[0][0], ra0, rb[0], rb[2]);
            mma_f16(acc[0][1], ra0, rb[1], rb[3]);
            mma_f16(acc[1][0], ra1, rb[0], rb[2]);
            mma_f16(acc[1][1], ra1, rb[1], rb[3]);
        }

        __syncthreads();                       // all warps done reading buf
        if (tid == 0 && t + 2 < NTILES) {
            uint32_t mb = sb + S_MB + 8 * buf;
            MBAR_EXPECT(mb, 11264u);
            bulkcp(sb + S_B + boff, d_B16 + (size_t)(t + 2) * 11264, 11264u, mb);
        }

        // epilogue: pair-max tournament, store PAIR ids only (no selects)
        const int pb = (t * NT + cb0) >> 1;    // pair-id base
#pragma unroll
        for (int j = 0; j < 2; j++) {
            const int pid = pb + j * 4;
#pragma unroll
            for (int mt = 0; mt < 2; mt++) {
                const int s0 = mt * 2;
                const int s1 = mt * 2 + 1;
                float p0 = fmaxf(acc[mt][j][0], acc[mt][j][1]);   // row r
                float p1 = fmaxf(acc[mt][j][2], acc[mt][j][3]);   // row r+8
                if (p0 > b1[s0]) { b2[s0] = b1[s0]; i2[s0] = i1[s0]; b1[s0] = p0; i1[s0] = pid; }
                else if (p0 > b2[s0]) { b2[s0] = p0; i2[s0] = pid; }
                if (p1 > b1[s1]) { b2[s1] = b1[s1]; i2[s1] = i1[s1]; b1[s1] = p1; i1[s1] = pid; }
                else if (p1 > b2[s1]) { b2[s1] = p1; i2[s1] = pid; }
            }
        }
    }

    // quad merge (lanes sharing l>>2 hold same rows)
#pragma unroll
    for (int s = 0; s < 4; s++) {
#pragma unroll
        for (int off = 1; off <= 2; off <<= 1) {
            float t1 = __shfl_xor_sync(0xFFFFFFFFu, b1[s], off);
            int   j1 = __shfl_xor_sync(0xFFFFFFFFu, i1[s], off);
            float t2 = __shfl_xor_sync(0xFFFFFFFFu, b2[s], off);
            int   j2 = __shfl_xor_sync(0xFFFFFFFFu, i2[s], off);
            if (t1 > b1[s]) {
                float nb2 = fmaxf(b1[s], t2);
                int   ni2 = (t2 > b1[s]) ? j2 : i1[s];
                b1[s] = t1; i1[s] = j1; b2[s] = nb2; i2[s] = ni2;
            } else if (t1 > b2[s]) {
                b2[s] = t1; i2[s] = j1;
            }
        }
    }

    // cross-N-warp merge via smem (reuse B region; all reads done)
    float4* red = (float4*)(smem + S_B);       // [128 rows][4 wn]
    if ((l & 3) == 0) {
#pragma unroll
        for (int s = 0; s < 4; s++) {
            int row = wm * 32 + (s >> 1) * 16 + (s & 1) * 8 + (l >> 2);
            red[row * 4 + wn] = make_float4(b1[s], __int_as_float(i1[s]),
                                            b2[s], __int_as_float(i2[s]));
        }
    }
    __syncthreads();
    if (tid < MT) {
        float s1 = -3.4e38f, s2 = -3.4e38f;
        int   k1 = 0, k2 = 0;
#pragma unroll
        for (int w = 0; w < 4; w++) {
            float4 V = red[tid * 4 + w];
            float t1 = V.x, t2 = V.z;
            int   j1 = __float_as_int(V.y), j2 = __float_as_int(V.w);
            if (t1 > s1) {
                float n2v = fmaxf(s1, t2);
                int   n2x = (t2 > s1) ? j2 : k1;
                s1 = t1; k1 = j1; s2 = n2v; k2 = n2x;
            } else if (t1 > s2) {
                s2 = t1; k2 = j1;
            }
        }
        d_cand[m0 + tid] = make_int2(k1, k2);   // two PAIR ids
    }
}

// ---------------------------------------------------------------------------
// finalize: exact rescore of 4 candidates (2 pairs, reference rounding) + gather
// ---------------------------------------------------------------------------
__global__ void __launch_bounds__(128) finalize(const float* __restrict__ ze,
                                                const float* __restrict__ cb,
                                                float* __restrict__ out) {
    __shared__ int bx[64];
    const int tid = threadIdx.x;
    const int n0  = blockIdx.x * 64;
    const int b   = n0 >> 12;
    const int hw0 = n0 & 4095;

    if (tid < 64) {
        const int n  = n0 + tid;
        const int hw = hw0 + tid;
        float x[DIM];
#pragma unroll
        for (int d = 0; d < DIM; d++)
            x[d] = ze[(size_t)(b * DIM + d) * 4096 + hw];
        float nx = 0.f;
#pragma unroll
        for (int d = 0; d < DIM; d++)
            nx = __fadd_rn(nx, __fmul_rn(x[d], x[d]));
        int2 cd = d_cand[n];
        int pa = min(cd.x, cd.y), pb = max(cd.x, cd.y);
        int cands[4] = {2 * pa, 2 * pa + 1, 2 * pb, 2 * pb + 1};  // ascending
        float bd = 3.4e38f;
        int   bi = 0x7fffffff;
#pragma unroll
        for (int q = 0; q < 4; q++) {
            int k = cands[q];
            const float* r = cb + (size_t)k * DIM;
            float m = 0.f;
#pragma unroll
            for (int d = 0; d < DIM; d++)
                m = __fmaf_rn(x[d], r[d], m);
            float d2 = __fadd_rn(__fadd_rn(nx, -__fmul_rn(2.0f, m)), d_cn[k]);
            if (d2 < bd || (d2 == bd && k < bi)) { bd = d2; bi = k; }
        }
        bx[tid] = bi;
    }
    __syncthreads();

    float* ob = out + (size_t)b * DIM * 4096 + hw0;
#pragma unroll
    for (int it = 0; it < 32; it++) {
        int e = tid + it * 128;
        int nl = e & 63, d = e >> 6;
        ob[(size_t)d * 4096 + nl] = cb[(size_t)bx[nl] * DIM + d];
    }
}

extern "C" void kernel_launch(void* const* d_in, const int* in_sizes, int n_in,
                              void* d_out, int out_size) {
    const float* ze = (const float*)d_in[0];   // [8,64,64,64] f32
    const float* cb = (const float*)d_in[1];   // [8192,64] f32
    float* out = (float*)d_out;

    cudaFuncSetAttribute(gemm_kernel, cudaFuncAttributeMaxDynamicSharedMemorySize,
                         SMEM_G);

    prep_cn<<<KC / 256, 256>>>(cb);
    prep_A<<<NP / 128, 256>>>(ze);
    prep_B<<<(KC * ROWW) / 256, 256>>>(cb);
    gemm_kernel<<<NP / MT, GT, SMEM_G>>>();
    finalize<<<NP / 64, 128>>>(ze, cb, out);
}